// round 8
// baseline (speedup 1.0000x reference)
#include <cuda_runtime.h>
#include <math.h>
#include <stdint.h>

// ---------------------------------------------------------------------------
// SparseMoE on GB300 (sm_103a) — R8
//   R7 lesson: harness PTX phase targets compute_103 (no 'a') -> tcgen05
//   unavailable. Stay on mma.sync tf32; close R6's latency gap instead.
//   R8: register double-buffered fragment pipeline (load kk+1 while mma kk,
//   last mma before the stage barrier), in-loop rna-tf32 cvt (drops xprep),
//   GEMM2 writes straight to out via atomicAdd (2-term add = deterministic).
// ---------------------------------------------------------------------------

#define HIDDEN 1024
#define INTER  4096
#define NEXP   8
#define MAXT   4096
#define MAXPAIRS (MAXT*2)

#define TM 128
#define TN 256
#define TK 32
#define APITCH 36                     // %32==4 -> A frag LDS.32 conflict-free
#define BPITCH 264                    // %32==8 -> B frag LDS.32 conflict-free
#define ABYTES (TM*APITCH*4)          // 18432
#define BBYTES (TK*BPITCH*4)          // 33792
#define STAGE_BYTES (ABYTES+BBYTES)   // 52224
#define NSTAGE 3                      // 156672 B dynamic smem, 1 CTA/SM

// ---- device scratch ----
__device__ int2   g_tsel[MAXT];
__device__ float2 g_tw[MAXT];
__device__ int    g_rowtok[MAXPAIRS];
__device__ float  g_roww[MAXPAIRS];
__device__ int    g_count[NEXP];
__device__ int    g_offset[NEXP];
__device__ float  g_h1[(size_t)MAXPAIRS * INTER];   // tf32-rounded gelu rows

// ---------------------------------------------------------------------------
// helpers
// ---------------------------------------------------------------------------
__device__ __forceinline__ uint32_t f2tf32(float f) {
    uint32_t r;
    asm("cvt.rna.tf32.f32 %0, %1;" : "=r"(r) : "f"(f));
    return r;
}
__device__ __forceinline__ void mma_tf32(float c[4],
                                         const uint32_t a[4],
                                         const uint32_t b[2]) {
    asm volatile(
        "mma.sync.aligned.m16n8k8.row.col.f32.tf32.tf32.f32 "
        "{%0,%1,%2,%3}, {%4,%5,%6,%7}, {%8,%9}, {%0,%1,%2,%3};\n"
        : "+f"(c[0]), "+f"(c[1]), "+f"(c[2]), "+f"(c[3])
        : "r"(a[0]), "r"(a[1]), "r"(a[2]), "r"(a[3]),
          "r"(b[0]), "r"(b[1]));
}
__device__ __forceinline__ float gelu_exact(float x) {
    return 0.5f * x * (1.0f + erff(x * 0.70710678118654752f));
}
__device__ __forceinline__ void cp16(uint32_t dst, const void* src) {
    asm volatile("cp.async.cg.shared.global [%0], [%1], 16;\n" :: "r"(dst), "l"(src));
}
__device__ __forceinline__ void cp_commit() {
    asm volatile("cp.async.commit_group;\n");
}
template <int N> __device__ __forceinline__ void cp_wait() {
    asm volatile("cp.async.wait_group %0;\n" :: "n"(N));
}

// ---------------------------------------------------------------------------
// 0) zero the MLP-output region (graph replays must not accumulate atomics)
// ---------------------------------------------------------------------------
__global__ void zero_kernel(float* __restrict__ out) {
    size_t i = (size_t)blockIdx.x * blockDim.x + threadIdx.x;
    ((float4*)out)[i] = make_float4(0.f, 0.f, 0.f, 0.f);
}

// ---------------------------------------------------------------------------
// 1) router
// ---------------------------------------------------------------------------
__global__ void router_kernel(const float* __restrict__ x,
                              const float* __restrict__ gw,
                              float* __restrict__ out_logits,
                              int write_logits) {
    int t = blockIdx.x;
    __shared__ float sx[HIDDEN];
    __shared__ float slog[NEXP];

    int tid = threadIdx.x;
    ((float4*)sx)[tid] = ((const float4*)(x + (size_t)t * HIDDEN))[tid];
    __syncthreads();

    int e = tid >> 5;
    int lane = tid & 31;
    float acc = 0.f;
    #pragma unroll 8
    for (int i = lane; i < HIDDEN; i += 32)
        acc += sx[i] * gw[i * NEXP + e];
    #pragma unroll
    for (int o = 16; o > 0; o >>= 1)
        acc += __shfl_down_sync(0xffffffffu, acc, o);
    if (lane == 0) slog[e] = acc;
    __syncthreads();

    if (tid == 0) {
        float l[NEXP];
        float m = -1e30f;
        #pragma unroll
        for (int i = 0; i < NEXP; i++) { l[i] = slog[i]; m = fmaxf(m, l[i]); }
        float p[NEXP];
        #pragma unroll
        for (int i = 0; i < NEXP; i++) p[i] = __expf(l[i] - m);
        int i1 = 0;
        #pragma unroll
        for (int i = 1; i < NEXP; i++) if (p[i] > p[i1]) i1 = i;
        int i2 = (i1 == 0) ? 1 : 0;
        #pragma unroll
        for (int i = 0; i < NEXP; i++)
            if (i != i1 && p[i] > p[i2]) i2 = i;
        float s = p[i1] + p[i2];
        g_tsel[t] = make_int2(i1, i2);
        g_tw[t]   = make_float2(p[i1] / s, p[i2] / s);
    }
    if (write_logits && tid < NEXP)
        out_logits[(size_t)t * NEXP + tid] = slog[tid];
}

// ---------------------------------------------------------------------------
// 2) deterministic compaction (Hillis-Steele scan, no atomics)
// ---------------------------------------------------------------------------
__global__ void scan_kernel(int T) {
    __shared__ int s[1024 * NEXP];
    __shared__ int s_off[NEXP];
    int tid = threadIdx.x;
    int tp = T / 1024;
    int t0 = tid * tp;

    int loc[NEXP];
    #pragma unroll
    for (int e = 0; e < NEXP; e++) loc[e] = 0;

    int2  sel[4];
    float2 wt[4];
    for (int j = 0; j < tp; j++) {
        sel[j] = g_tsel[t0 + j];
        wt[j]  = g_tw[t0 + j];
        loc[sel[j].x]++;
        loc[sel[j].y]++;
    }

    int val[NEXP];
    #pragma unroll
    for (int e = 0; e < NEXP; e++) { val[e] = loc[e]; s[tid * NEXP + e] = val[e]; }

    for (int off = 1; off < 1024; off <<= 1) {
        __syncthreads();
        int add[NEXP];
        #pragma unroll
        for (int e = 0; e < NEXP; e++)
            add[e] = (tid >= off) ? s[(tid - off) * NEXP + e] : 0;
        __syncthreads();
        #pragma unroll
        for (int e = 0; e < NEXP; e++) { val[e] += add[e]; s[tid * NEXP + e] = val[e]; }
    }
    __syncthreads();

    if (tid == 0) {
        int o = 0;
        for (int e = 0; e < NEXP; e++) {
            int tot = s[1023 * NEXP + e];
            g_count[e]  = tot;
            g_offset[e] = o;
            s_off[e]    = o;
            o += tot;
        }
    }
    __syncthreads();

    int pos[NEXP];
    #pragma unroll
    for (int e = 0; e < NEXP; e++) pos[e] = s_off[e] + (val[e] - loc[e]);

    for (int j = 0; j < tp; j++) {
        int t = t0 + j;
        int e0 = sel[j].x, e1 = sel[j].y;
        int i0 = pos[e0]++;
        g_rowtok[i0] = t * 2;     g_roww[i0] = wt[j].x;
        int i1 = pos[e1]++;
        g_rowtok[i1] = t * 2 + 1; g_roww[i1] = wt[j].y;
    }
}

// ---------------------------------------------------------------------------
// 3/4) grouped GEMM, tf32 mma.sync, 128x256x32 tiles, 3-stage cp.async,
//      register double-buffered fragments.
//   MODE 1: A = x gathered rows -> h1 = tf32(gelu(.))
//   MODE 2: A = g_h1 rows       -> atomicAdd(out, wgt * .)
// ---------------------------------------------------------------------------
template <int MODE>
__global__ __launch_bounds__(256, 1)
void moe_gemm(const float* __restrict__ Xglob,
              const float* __restrict__ Wglob,
              float* __restrict__ out) {
    constexpr int K  = (MODE == 1) ? HIDDEN : INTER;
    constexpr int N  = (MODE == 1) ? INTER  : HIDDEN;
    constexpr int KI = K / TK;

    extern __shared__ char smem_raw[];
    const int e = blockIdx.z;
    const int count = g_count[e];
    const int m0 = blockIdx.y * TM;
    if (m0 >= count) return;
    const int off = g_offset[e];
    const int n0 = blockIdx.x * TN;
    const float* W = Wglob + (size_t)e * K * N;

    const float* Aglob = (MODE == 1) ? Xglob : (const float*)g_h1;

    const int tid  = threadIdx.x;
    const int lane = tid & 31;
    const int warp = tid >> 5;
    const int q    = lane & 3;
    const int lr   = lane >> 2;
    const int wrow = (warp & 1) * 64;
    const int wcol = (warp >> 1) * 64;

    const uint32_t sbase = (uint32_t)__cvta_generic_to_shared(smem_raw);

    // A source row pointers (4 staged rows per thread)
    const float* arow[4];
    #pragma unroll
    for (int p = 0; p < 4; p++) {
        int r  = (tid >> 3) + 32 * p;
        int gr = m0 + r;
        int rr = (gr < count) ? gr : (count - 1);
        if (MODE == 1) {
            int tok = g_rowtok[off + rr] >> 1;
            arow[p] = Aglob + (size_t)tok * K;
        } else {
            arow[p] = Aglob + (size_t)(off + rr) * K;
        }
    }
    const int ac = (tid & 7) * 4;     // float col of this thread's 16B A chunk
    const int bk = tid >> 3;          // B k-row
    const int bn = (tid & 7) * 4;     // B base float col (chunks stride 32)

    auto issue_stage = [&](int ki) {
        const uint32_t sa = sbase + (ki % NSTAGE) * STAGE_BYTES;
        const uint32_t sb = sa + ABYTES;
        const int k0 = ki * TK;
        #pragma unroll
        for (int p = 0; p < 4; p++) {
            int r = (tid >> 3) + 32 * p;
            cp16(sa + (uint32_t)(r * APITCH + ac) * 4, arow[p] + k0 + ac);
        }
        const float* bsrc = W + (size_t)(k0 + bk) * N + n0 + bn;
        #pragma unroll
        for (int j = 0; j < 8; j++)
            cp16(sb + (uint32_t)(bk * BPITCH + bn + 32 * j) * 4, bsrc + 32 * j);
    };

    float c[4][8][4];
    #pragma unroll
    for (int i = 0; i < 4; i++)
        #pragma unroll
        for (int j = 0; j < 8; j++)
            #pragma unroll
            for (int r = 0; r < 4; r++) c[i][j][r] = 0.f;

    uint32_t a[2][4][4], b[2][8][2];

    auto load_frag = [&](int buf, const char* sp, int kk) {
        const float* As = (const float*)sp;
        const float* Bs = (const float*)(sp + ABYTES);
        const int kb = kk * 8;
        #pragma unroll
        for (int im = 0; im < 4; im++) {
            int row = wrow + im * 16 + lr;
            a[buf][im][0] = f2tf32(As[row * APITCH + kb + q]);
            a[buf][im][1] = f2tf32(As[(row + 8) * APITCH + kb + q]);
            a[buf][im][2] = f2tf32(As[row * APITCH + kb + q + 4]);
            a[buf][im][3] = f2tf32(As[(row + 8) * APITCH + kb + q + 4]);
        }
        #pragma unroll
        for (int jn = 0; jn < 8; jn++) {
            int nn = wcol + jn * 8 + lr;
            b[buf][jn][0] = f2tf32(Bs[(kb + q) * BPITCH + nn]);
            b[buf][jn][1] = f2tf32(Bs[(kb + q + 4) * BPITCH + nn]);
        }
    };
    auto mma_all = [&](int buf) {
        #pragma unroll
        for (int im = 0; im < 4; im++)
            #pragma unroll
            for (int jn = 0; jn < 8; jn++)
                mma_tf32(c[im][jn], a[buf][im], b[buf][jn]);
    };

    issue_stage(0); cp_commit();
    issue_stage(1); cp_commit();
    issue_stage(2); cp_commit();
    cp_wait<2>();
    __syncthreads();
    load_frag(0, smem_raw, 0);

    for (int i = 0; i < KI; i++) {
        const char* sp = smem_raw + (i % NSTAGE) * STAGE_BYTES;
        #pragma unroll
        for (int kk = 0; kk < 4; kk++) {
            const int cur = kk & 1;
            if (kk < 3) {
                load_frag(cur ^ 1, sp, kk + 1);
                mma_all(cur);
            } else {
                mma_all(cur);               // overlap tensor with barrier
                if (i + 1 < KI) {
                    cp_wait<1>();           // stage i+1 fully arrived
                    __syncthreads();        // all warps done reading stage i
                    if (i + 3 < KI) issue_stage(i + 3);
                    cp_commit();
                    load_frag(cur ^ 1,
                              smem_raw + ((i + 1) % NSTAGE) * STAGE_BYTES, 0);
                }
            }
        }
    }

    // epilogue
    #pragma unroll
    for (int im = 0; im < 4; im++) {
        #pragma unroll
        for (int half = 0; half < 2; half++) {
            int m  = wrow + im * 16 + lr + 8 * half;
            int gr = m0 + m;
            if (gr >= count) continue;
            if (MODE == 1) {
                size_t base = (size_t)(off + gr) * N;
                #pragma unroll
                for (int jn = 0; jn < 8; jn++) {
                    int n = n0 + wcol + jn * 8 + q * 2;
                    float2 o;
                    o.x = __uint_as_float(f2tf32(gelu_exact(c[im][jn][half * 2])));
                    o.y = __uint_as_float(f2tf32(gelu_exact(c[im][jn][half * 2 + 1])));
                    *(float2*)((float*)g_h1 + base + n) = o;
                }
            } else {
                int tok   = g_rowtok[off + gr] >> 1;
                float wgt = g_roww[off + gr];
                size_t base = (size_t)tok * N;
                #pragma unroll
                for (int jn = 0; jn < 8; jn++) {
                    int n = n0 + wcol + jn * 8 + q * 2;
                    atomicAdd(out + base + n,     wgt * c[im][jn][half * 2]);
                    atomicAdd(out + base + n + 1, wgt * c[im][jn][half * 2 + 1]);
                }
            }
        }
    }
}

// ---------------------------------------------------------------------------
extern "C" void kernel_launch(void* const* d_in, const int* in_sizes, int n_in,
                              void* d_out, int out_size) {
    const float* x  = (const float*)d_in[0];
    const float* gw = (const float*)d_in[1];
    const float* w1 = (const float*)d_in[2];
    const float* w2 = (const float*)d_in[3];
    float* out = (float*)d_out;

    const int T = in_sizes[0] / HIDDEN;

    int write_logits = (out_size >= T * HIDDEN + T * NEXP) ? 1 : 0;
    float* logits_ptr = out + (size_t)T * HIDDEN;

    const int smem_bytes = NSTAGE * STAGE_BYTES;
    cudaFuncSetAttribute(moe_gemm<1>, cudaFuncAttributeMaxDynamicSharedMemorySize, smem_bytes);
    cudaFuncSetAttribute(moe_gemm<2>, cudaFuncAttributeMaxDynamicSharedMemorySize, smem_bytes);

    // 0) zero MLP-output region (atomics accumulate across graph replays)
    zero_kernel<<<T * HIDDEN / 4 / 256, 256>>>(out);

    // 1) router + 2) compaction
    router_kernel<<<T, 256>>>(x, gw, logits_ptr, write_logits);
    scan_kernel<<<1, 1024>>>(T);

    // 3) GEMM1: h1 = tf32(gelu(x_g @ w1[e]))   K=HIDDEN, N=INTER
    {
        dim3 grid(INTER / TN, (T + TM - 1) / TM, NEXP);
        moe_gemm<1><<<grid, 256, smem_bytes>>>(x, w1, out);
    }

    // 4) GEMM2: out += wgt * (h1 @ w2[e])      K=INTER, N=HIDDEN
    {
        dim3 grid(HIDDEN / TN, (T + TM - 1) / TM, NEXP);
        moe_gemm<2><<<grid, 256, smem_bytes>>>(nullptr, w2, out);
    }
}

// round 9
// speedup vs baseline: 1.9881x; 1.9881x over previous
#include <cuda_runtime.h>
#include <cuda_fp16.h>
#include <math.h>
#include <stdint.h>

// ---------------------------------------------------------------------------
// SparseMoE on GB300 (sm_103a) — R9: fp16 mma.sync m16n8k16
//   fp16 mantissa == tf32 mantissa (11 bits) -> same accuracy class, 2x rate,
//   half the smem/gmem traffic. All operands pre-converted to fp16 with a
//   k-pair permutation (16-group order 0,1,8,9,2,3,10,11,4,5,12,13,6,7,14,15)
//   so every A/B fragment is ONE LDS.64. Pitch 80B -> uniform 2-phase banks.
// ---------------------------------------------------------------------------

#define HIDDEN 1024
#define INTER  4096
#define NEXP   8
#define MAXT   4096
#define MAXPAIRS (MAXT*2)

#define TM 128
#define TN 256
#define TK 32                      // k per smem stage (2 x k16 mma chunks)
#define APITCH 80                  // bytes per A smem row (64 data + 16 pad)
#define BPITCH 80                  // bytes per B smem row
#define ABYTES (TM*APITCH)         // 10240
#define BBYTES (TN*BPITCH)         // 20480
#define STAGE_BYTES (ABYTES+BBYTES)// 30720
#define NSTAGE 4                   // 122880 B dynamic smem

// ---- device scratch ----
__device__ int2   g_tsel[MAXT];
__device__ float2 g_tw[MAXT];
__device__ int    g_rowtok[MAXPAIRS];
__device__ float  g_roww[MAXPAIRS];
__device__ int    g_count[NEXP];
__device__ int    g_offset[NEXP];
__device__ __half g_xh[(size_t)MAXT * HIDDEN];           // fp16 x, k-permuted
__device__ __half g_w1h[(size_t)NEXP * INTER * HIDDEN];  // w1^T [e][n][k] perm
__device__ __half g_w2h[(size_t)NEXP * HIDDEN * INTER];  // w2^T [e][n][k] perm
__device__ __half g_h1h[(size_t)MAXPAIRS * INTER];       // fp16 gelu rows, perm

// ---------------------------------------------------------------------------
// helpers
// ---------------------------------------------------------------------------
__device__ __forceinline__ float gelu_exact(float x) {
    return 0.5f * x * (1.0f + erff(x * 0.70710678118654752f));
}
__device__ __forceinline__ void cp16(uint32_t dst, const void* src) {
    asm volatile("cp.async.cg.shared.global [%0], [%1], 16;\n" :: "r"(dst), "l"(src));
}
__device__ __forceinline__ void cp_commit() {
    asm volatile("cp.async.commit_group;\n");
}
template <int N> __device__ __forceinline__ void cp_wait() {
    asm volatile("cp.async.wait_group %0;\n" :: "n"(N));
}
// c += A(16x16) * B(16x8) fp16 inputs, f32 accum
__device__ __forceinline__ void mma_fp16(float c[4],
                                         uint32_t a0, uint32_t a1,
                                         uint32_t a2, uint32_t a3,
                                         uint32_t b0, uint32_t b1) {
    asm volatile(
        "mma.sync.aligned.m16n8k16.row.col.f32.f16.f16.f32 "
        "{%0,%1,%2,%3}, {%4,%5,%6,%7}, {%8,%9}, {%0,%1,%2,%3};\n"
        : "+f"(c[0]), "+f"(c[1]), "+f"(c[2]), "+f"(c[3])
        : "r"(a0), "r"(a1), "r"(a2), "r"(a3), "r"(b0), "r"(b1));
}
// pack two rounded halves
__device__ __forceinline__ uint32_t pack_h2(float x, float y) {
    __half2 h = __floats2half2_rn(x, y);
    return *(uint32_t*)&h;
}

// ---------------------------------------------------------------------------
// 0) zero MLP-output region (atomics accumulate across graph replays)
// ---------------------------------------------------------------------------
__global__ void zero_kernel(float* __restrict__ out) {
    size_t i = (size_t)blockIdx.x * blockDim.x + threadIdx.x;
    ((float4*)out)[i] = make_float4(0.f, 0.f, 0.f, 0.f);
}

// ---------------------------------------------------------------------------
// 1) router (unchanged; fp32 exact)
// ---------------------------------------------------------------------------
__global__ void router_kernel(const float* __restrict__ x,
                              const float* __restrict__ gw,
                              float* __restrict__ out_logits,
                              int write_logits) {
    int t = blockIdx.x;
    __shared__ float sx[HIDDEN];
    __shared__ float slog[NEXP];

    int tid = threadIdx.x;
    ((float4*)sx)[tid] = ((const float4*)(x + (size_t)t * HIDDEN))[tid];
    __syncthreads();

    int e = tid >> 5;
    int lane = tid & 31;
    float acc = 0.f;
    #pragma unroll 8
    for (int i = lane; i < HIDDEN; i += 32)
        acc += sx[i] * gw[i * NEXP + e];
    #pragma unroll
    for (int o = 16; o > 0; o >>= 1)
        acc += __shfl_down_sync(0xffffffffu, acc, o);
    if (lane == 0) slog[e] = acc;
    __syncthreads();

    if (tid == 0) {
        float l[NEXP];
        float m = -1e30f;
        #pragma unroll
        for (int i = 0; i < NEXP; i++) { l[i] = slog[i]; m = fmaxf(m, l[i]); }
        float p[NEXP];
        #pragma unroll
        for (int i = 0; i < NEXP; i++) p[i] = __expf(l[i] - m);
        int i1 = 0;
        #pragma unroll
        for (int i = 1; i < NEXP; i++) if (p[i] > p[i1]) i1 = i;
        int i2 = (i1 == 0) ? 1 : 0;
        #pragma unroll
        for (int i = 0; i < NEXP; i++)
            if (i != i1 && p[i] > p[i2]) i2 = i;
        float s = p[i1] + p[i2];
        g_tsel[t] = make_int2(i1, i2);
        g_tw[t]   = make_float2(p[i1] / s, p[i2] / s);
    }
    if (write_logits && tid < NEXP)
        out_logits[(size_t)t * NEXP + tid] = slog[tid];
}

// ---------------------------------------------------------------------------
// 2) deterministic compaction (unchanged)
// ---------------------------------------------------------------------------
__global__ void scan_kernel(int T) {
    __shared__ int s[1024 * NEXP];
    __shared__ int s_off[NEXP];
    int tid = threadIdx.x;
    int tp = T / 1024;
    int t0 = tid * tp;

    int loc[NEXP];
    #pragma unroll
    for (int e = 0; e < NEXP; e++) loc[e] = 0;

    int2  sel[4];
    float2 wt[4];
    for (int j = 0; j < tp; j++) {
        sel[j] = g_tsel[t0 + j];
        wt[j]  = g_tw[t0 + j];
        loc[sel[j].x]++;
        loc[sel[j].y]++;
    }

    int val[NEXP];
    #pragma unroll
    for (int e = 0; e < NEXP; e++) { val[e] = loc[e]; s[tid * NEXP + e] = val[e]; }

    for (int off = 1; off < 1024; off <<= 1) {
        __syncthreads();
        int add[NEXP];
        #pragma unroll
        for (int e = 0; e < NEXP; e++)
            add[e] = (tid >= off) ? s[(tid - off) * NEXP + e] : 0;
        __syncthreads();
        #pragma unroll
        for (int e = 0; e < NEXP; e++) { val[e] += add[e]; s[tid * NEXP + e] = val[e]; }
    }
    __syncthreads();

    if (tid == 0) {
        int o = 0;
        for (int e = 0; e < NEXP; e++) {
            int tot = s[1023 * NEXP + e];
            g_count[e]  = tot;
            g_offset[e] = o;
            s_off[e]    = o;
            o += tot;
        }
    }
    __syncthreads();

    int pos[NEXP];
    #pragma unroll
    for (int e = 0; e < NEXP; e++) pos[e] = s_off[e] + (val[e] - loc[e]);

    for (int j = 0; j < tp; j++) {
        int t = t0 + j;
        int e0 = sel[j].x, e1 = sel[j].y;
        int i0 = pos[e0]++;
        g_rowtok[i0] = t * 2;     g_roww[i0] = wt[j].x;
        int i1 = pos[e1]++;
        g_rowtok[i1] = t * 2 + 1; g_roww[i1] = wt[j].y;
    }
}

// ---------------------------------------------------------------------------
// 3) xprep: x (f32) -> g_xh (fp16), 16-group k-permutation.
//    Within each 16: stored order is 0,1,8,9, 2,3,10,11, 4,5,12,13, 6,7,14,15
//    so (2q,2q+1,2q+8,2q+9) sit in one 8B slot -> single LDS.64 fragments.
//    u32 slot w (0..7): source pair j0 = (w>>1)*2 + (w&1)*8.
// ---------------------------------------------------------------------------
__global__ void xprep_kernel(const float* __restrict__ x) {
    size_t gi = (size_t)blockIdx.x * blockDim.x + threadIdx.x;  // 16-group idx
    const float* src = x + gi * 16;
    uint32_t* dst = (uint32_t*)g_xh + gi * 8;
    float v[16];
    #pragma unroll
    for (int j = 0; j < 16; j += 4) {
        float4 f = *(const float4*)(src + j);
        v[j] = f.x; v[j + 1] = f.y; v[j + 2] = f.z; v[j + 3] = f.w;
    }
    #pragma unroll
    for (int w = 0; w < 8; w++) {
        int j0 = ((w >> 1) * 2) + ((w & 1) * 8);
        dst[w] = pack_h2(v[j0], v[j0 + 1]);
    }
}

// ---------------------------------------------------------------------------
// 4) wprep: w [e][K][N] f32 -> wt [e][N][K] fp16, k-permuted (32x32 tiles)
// ---------------------------------------------------------------------------
template <int WS>
__global__ void wprep_kernel(const float* __restrict__ w, int K, int N) {
    __shared__ float s[32][34];       // [k][n], pitch 34 -> conflict-free reads
    __half* wt = (WS == 1) ? (__half*)g_w1h : (__half*)g_w2h;
    const float* We = w + (size_t)blockIdx.z * K * N;
    __half* Wte = wt + (size_t)blockIdx.z * (size_t)K * N;
    int k0 = blockIdx.x * 32, n0 = blockIdx.y * 32;
    int tid = threadIdx.x;
    {
        int kr = tid >> 3, c = tid & 7;
        float4 v = *(const float4*)(We + (size_t)(k0 + kr) * N + n0 + 4 * c);
        s[kr][4 * c + 0] = v.x;
        s[kr][4 * c + 1] = v.y;
        s[kr][4 * c + 2] = v.z;
        s[kr][4 * c + 3] = v.w;
    }
    __syncthreads();
    int nl = tid >> 3, w2 = tid & 7;
    uint32_t* dst = (uint32_t*)(Wte + (size_t)(n0 + nl) * K + k0);
    #pragma unroll
    for (int h = 0; h < 2; h++) {
        int ww = w2 + 8 * h;                 // u32 slot 0..15 (two 16-groups)
        int kk16 = ww >> 3;
        int w8 = ww & 7;
        int j0 = ((w8 >> 1) * 2) + ((w8 & 1) * 8) + kk16 * 16;
        dst[ww] = pack_h2(s[j0][nl], s[j0 + 1][nl]);
    }
}

// ---------------------------------------------------------------------------
// 5/6) grouped GEMM — fp16 mma.sync m16n8k16, 128x256x32 tiles,
//      4-stage cp.async, 8 warps (2m x 4n, warp tile 64x64).
//   MODE 1: A = g_xh gathered rows -> g_h1h = fp16(gelu(.)), k-permuted
//   MODE 2: A = g_h1h rows         -> atomicAdd(out, wgt * .)
// ---------------------------------------------------------------------------
template <int MODE>
__global__ __launch_bounds__(256, 1)
void moe_gemm(float* __restrict__ out) {
    constexpr int K  = (MODE == 1) ? HIDDEN : INTER;
    constexpr int N  = (MODE == 1) ? INTER  : HIDDEN;
    constexpr int KI = K / TK;

    extern __shared__ char smem_raw[];
    const int e = blockIdx.z;
    const int count = g_count[e];
    const int m0 = blockIdx.y * TM;
    if (m0 >= count) return;
    const int off = g_offset[e];
    const int n0 = blockIdx.x * TN;

    const __half* Aglob = (MODE == 1) ? (const __half*)g_xh : (const __half*)g_h1h;
    const __half* Wt = ((MODE == 1) ? (const __half*)g_w1h : (const __half*)g_w2h)
                       + (size_t)e * (size_t)K * N;

    const int tid  = threadIdx.x;
    const int lane = tid & 31;
    const int warp = tid >> 5;
    const int q    = lane & 3;
    const int lr   = lane >> 2;
    const int wrow = (warp & 1) * 64;
    const int wcol = (warp >> 1) * 64;

    const uint32_t sbase = (uint32_t)__cvta_generic_to_shared(smem_raw);

    // A source: one gathered row per thread (row tid>>1, two 16B chunks)
    const __half* arow;
    {
        int r  = tid >> 1;
        int gr = m0 + r;
        int rr = (gr < count) ? gr : (count - 1);
        int src = (MODE == 1) ? (g_rowtok[off + rr] >> 1) : (off + rr);
        arow = Aglob + (size_t)src * K;
    }
    const int ac = (tid & 1) * 2;          // first of two 16B chunks in row

    auto issue_stage = [&](int ki) {
        const uint32_t sa = sbase + (ki % NSTAGE) * STAGE_BYTES;
        const uint32_t sb = sa + ABYTES;
        const int kb = ki * 64;            // byte offset of k-window in row
        {
            int r = tid >> 1;
            cp16(sa + (uint32_t)(r * APITCH + ac * 16),
                 (const char*)arow + kb + ac * 16);
            cp16(sa + (uint32_t)(r * APITCH + (ac + 1) * 16),
                 (const char*)arow + kb + (ac + 1) * 16);
        }
        {
            int c = tid & 3;
            #pragma unroll
            for (int j = 0; j < 4; j++) {
                int n = (tid >> 2) + 64 * j;
                cp16(sb + (uint32_t)(n * BPITCH + c * 16),
                     (const char*)(Wt + (size_t)(n0 + n) * K) + kb + c * 16);
            }
        }
    };

    float c[4][8][4];
    #pragma unroll
    for (int i = 0; i < 4; i++)
        #pragma unroll
        for (int j = 0; j < 8; j++)
            #pragma unroll
            for (int r = 0; r < 4; r++) c[i][j][r] = 0.f;

    issue_stage(0); cp_commit();
    issue_stage(1); cp_commit();
    issue_stage(2); cp_commit();

    for (int i = 0; i < KI; i++) {
        cp_wait<2>();
        __syncthreads();
        if (i + 3 < KI) issue_stage(i + 3);
        cp_commit();

        const char* sp = smem_raw + (i % NSTAGE) * STAGE_BYTES;
        const char* spB = sp + ABYTES;

        #pragma unroll
        for (int cc = 0; cc < 2; cc++) {          // two k16 chunks
            const int co = cc * 32 + q * 8;       // byte offset within row
            uint32_t a[4][4];
            #pragma unroll
            for (int im = 0; im < 4; im++) {
                int row = wrow + im * 16 + lr;
                uint2 v0 = *(const uint2*)(sp + row * APITCH + co);
                uint2 v1 = *(const uint2*)(sp + (row + 8) * APITCH + co);
                a[im][0] = v0.x;   // (lr,   k 2q,2q+1)
                a[im][1] = v1.x;   // (lr+8, k 2q,2q+1)
                a[im][2] = v0.y;   // (lr,   k 2q+8,2q+9)
                a[im][3] = v1.y;   // (lr+8, k 2q+8,2q+9)
            }
            uint32_t b[8][2];
            #pragma unroll
            for (int jn = 0; jn < 8; jn++) {
                int nn = wcol + jn * 8 + lr;
                uint2 v = *(const uint2*)(spB + nn * BPITCH + co);
                b[jn][0] = v.x;
                b[jn][1] = v.y;
            }
            #pragma unroll
            for (int im = 0; im < 4; im++)
                #pragma unroll
                for (int jn = 0; jn < 8; jn++)
                    mma_fp16(c[im][jn], a[im][0], a[im][1], a[im][2], a[im][3],
                             b[jn][0], b[jn][1]);
        }
    }

    // epilogue: c0,c1 = (lr, n 2q,2q+1); c2,c3 = (lr+8, same)
    #pragma unroll
    for (int im = 0; im < 4; im++) {
        #pragma unroll
        for (int half = 0; half < 2; half++) {
            int m  = wrow + im * 16 + lr + 8 * half;
            int gr = m0 + m;
            if (gr >= count) continue;
            if (MODE == 1) {
                // write fp16(gelu) in k-permuted layout for GEMM2's A reads
                __half* dst = (__half*)g_h1h + (size_t)(off + gr) * N;
                #pragma unroll
                for (int jn = 0; jn < 8; jn++) {
                    float v0 = gelu_exact(c[im][jn][half * 2]);
                    float v1 = gelu_exact(c[im][jn][half * 2 + 1]);
                    int pos = n0 + wcol + (jn >> 1) * 16 + q * 4 + (jn & 1) * 2;
                    *(uint32_t*)(dst + pos) = pack_h2(v0, v1);
                }
            } else {
                int info  = g_rowtok[off + gr];
                float wgt = g_roww[off + gr];
                float* dst = out + (size_t)(info >> 1) * N;
                #pragma unroll
                for (int jn = 0; jn < 8; jn++) {
                    int n = n0 + wcol + jn * 8 + q * 2;
                    atomicAdd(dst + n,     wgt * c[im][jn][half * 2]);
                    atomicAdd(dst + n + 1, wgt * c[im][jn][half * 2 + 1]);
                }
            }
        }
    }
}

// ---------------------------------------------------------------------------
extern "C" void kernel_launch(void* const* d_in, const int* in_sizes, int n_in,
                              void* d_out, int out_size) {
    const float* x  = (const float*)d_in[0];
    const float* gw = (const float*)d_in[1];
    const float* w1 = (const float*)d_in[2];
    const float* w2 = (const float*)d_in[3];
    float* out = (float*)d_out;

    const int T = in_sizes[0] / HIDDEN;

    int write_logits = (out_size >= T * HIDDEN + T * NEXP) ? 1 : 0;
    float* logits_ptr = out + (size_t)T * HIDDEN;

    const int smem_bytes = NSTAGE * STAGE_BYTES;
    cudaFuncSetAttribute(moe_gemm<1>, cudaFuncAttributeMaxDynamicSharedMemorySize, smem_bytes);
    cudaFuncSetAttribute(moe_gemm<2>, cudaFuncAttributeMaxDynamicSharedMemorySize, smem_bytes);

    // 0) zero MLP-output region
    zero_kernel<<<T * HIDDEN / 4 / 256, 256>>>(out);

    // 1) router + 2) compaction
    router_kernel<<<T, 256>>>(x, gw, logits_ptr, write_logits);
    scan_kernel<<<1, 1024>>>(T);

    // 3) x -> fp16 (k-permuted)
    xprep_kernel<<<T * (HIDDEN / 16) / 256, 256>>>(x);

    // 4) weights -> transposed fp16 (k-permuted)
    {
        dim3 g1(HIDDEN / 32, INTER / 32, NEXP);
        wprep_kernel<1><<<g1, 256>>>(w1, HIDDEN, INTER);
        dim3 g2(INTER / 32, HIDDEN / 32, NEXP);
        wprep_kernel<2><<<g2, 256>>>(w2, INTER, HIDDEN);
    }

    // 5) GEMM1: h1 = fp16(gelu(x_g @ w1[e]))   K=HIDDEN, N=INTER
    {
        dim3 grid(INTER / TN, MAXT / TM, NEXP);
        moe_gemm<1><<<grid, 256, smem_bytes>>>(out);
    }

    // 6) GEMM2: out += wgt * (h1 @ w2[e])      K=INTER, N=HIDDEN
    {
        dim3 grid(HIDDEN / TN, MAXT / TM, NEXP);
        moe_gemm<2><<<grid, 256, smem_bytes>>>(out);
    }
}